// round 2
// baseline (speedup 1.0000x reference)
#include <cuda_runtime.h>
#include <cstdint>

// ---------------------------------------------------------------------------
// AutoEncoder_32143535244000: Bahdanau-attention GRU decoder
// B=64, L=64, F=2048, EMB=256, UNITS=512, VOCAB=10001, T=52
// outputs: proba [B,T,VOCAB] (f32) then labels [B,T] (as f32) if room
// ---------------------------------------------------------------------------

#define B_SZ   64
#define L_SZ   64
#define FEATD  2048
#define EMB    256
#define UNITS  512
#define VOCAB  10001
#define TSTEPS 52
#define ML     (B_SZ*L_SZ)             // 4096
#define MTB    (TSTEPS*B_SZ)           // 3328
#define PADN   10048                   // fc2 N padded to mult of 64
#define NSPLIT 8                       // split-K for small GEMMs (K=512 -> 64/slice)
#define PROBA_ELEMS ((size_t)B_SZ*TSTEPS*VOCAB)

// ------------------------------- scratch -----------------------------------
__device__ float g_feat  [ML*EMB];            // 4 MB
__device__ float g_featW1[ML*UNITS];          // 8 MB
__device__ float g_h     [B_SZ*UNITS];
__device__ float g_x     [B_SZ*2*EMB];        // [ctx(256) | emb(256)]
__device__ float g_hW2p  [NSPLIT*B_SZ*UNITS];
__device__ float g_ghp   [NSPLIT*B_SZ*3*UNITS];
__device__ float g_gxp   [NSPLIT*B_SZ*3*UNITS];
__device__ float g_H     [MTB*UNITS];         // 6.8 MB
__device__ float g_F1    [MTB*UNITS];         // 6.8 MB
__device__ float g_fc2Wp [UNITS*PADN];        // 20.6 MB

// ----------------------------- helpers -------------------------------------
__device__ __forceinline__ unsigned long long pk2(float x) {
    unsigned long long r;
    unsigned int xi = __float_as_uint(x);
    asm("mov.b64 %0, {%1, %1};" : "=l"(r) : "r"(xi));
    return r;
}
__device__ __forceinline__ void fma2(unsigned long long &d,
                                     unsigned long long a, unsigned long long b) {
    asm("fma.rn.f32x2 %0, %1, %2, %0;" : "+l"(d) : "l"(a), "l"(b));
}
__device__ __forceinline__ float2 up2(unsigned long long v) {
    unsigned int lo, hi;
    asm("mov.b64 {%0, %1}, %2;" : "=r"(lo), "=r"(hi) : "l"(v));
    return make_float2(__uint_as_float(lo), __uint_as_float(hi));
}
__device__ __forceinline__ float fast_tanh(float x) {
    float e = __expf(2.0f * x);
    return 1.0f - __fdividef(2.0f, e + 1.0f);
}
__device__ __forceinline__ float fast_sigm(float x) {
    return __fdividef(1.0f, 1.0f + __expf(-x));
}

// ------------------------- big SGEMM (f32x2) --------------------------------
// C[M,N] = A[M,K] @ B[K,N](ldb) + bias ; BM=128 BN=64 BK=16, 128 thr, 8x8/thr
// EPI 0: +bias  | EPI 1: +bias, relu | EPI 2: proba remap (row t*64+b -> b*52+t, col<VOCAB)
template<int EPI>
__global__ __launch_bounds__(128)
void sgemm(const float* __restrict__ A, const float* __restrict__ B,
           const float* __restrict__ bias, float* __restrict__ C,
           int M, int N, int K, int ldb)
{
    __shared__ __align__(16) float As[16][128];
    __shared__ __align__(16) float Bs[16][64];
    const int tid = threadIdx.x;
    const int m0 = blockIdx.y * 128, n0 = blockIdx.x * 64;
    const int a_kf = tid & 3,  a_r  = tid >> 2;   // A: 4 float4 along K, 32 rows/pass
    const int b_nf = tid & 15, b_kr = tid >> 4;   // B: 16 float4 along N, 8 k/pass
    const int tm = tid >> 3, tn = tid & 7;
    unsigned long long acc[8][4] = {};

    for (int k0 = 0; k0 < K; k0 += 16) {
        #pragma unroll
        for (int p = 0; p < 4; ++p) {
            int row = a_r + p * 32;
            float4 v = *(const float4*)&A[(size_t)(m0 + row) * K + k0 + a_kf * 4];
            As[a_kf*4+0][row] = v.x; As[a_kf*4+1][row] = v.y;
            As[a_kf*4+2][row] = v.z; As[a_kf*4+3][row] = v.w;
        }
        #pragma unroll
        for (int p = 0; p < 2; ++p) {
            int kr = b_kr + p * 8;
            *(float4*)&Bs[kr][b_nf*4] =
                *(const float4*)&B[(size_t)(k0 + kr) * ldb + n0 + b_nf * 4];
        }
        __syncthreads();
        #pragma unroll
        for (int kk = 0; kk < 16; ++kk) {
            float4 a0 = *(const float4*)&As[kk][tm*8];
            float4 a1 = *(const float4*)&As[kk][tm*8+4];
            ulonglong2 b0 = *(const ulonglong2*)&Bs[kk][tn*8];
            ulonglong2 b1 = *(const ulonglong2*)&Bs[kk][tn*8+4];
            unsigned long long ap;
            ap = pk2(a0.x); fma2(acc[0][0],ap,b0.x); fma2(acc[0][1],ap,b0.y); fma2(acc[0][2],ap,b1.x); fma2(acc[0][3],ap,b1.y);
            ap = pk2(a0.y); fma2(acc[1][0],ap,b0.x); fma2(acc[1][1],ap,b0.y); fma2(acc[1][2],ap,b1.x); fma2(acc[1][3],ap,b1.y);
            ap = pk2(a0.z); fma2(acc[2][0],ap,b0.x); fma2(acc[2][1],ap,b0.y); fma2(acc[2][2],ap,b1.x); fma2(acc[2][3],ap,b1.y);
            ap = pk2(a0.w); fma2(acc[3][0],ap,b0.x); fma2(acc[3][1],ap,b0.y); fma2(acc[3][2],ap,b1.x); fma2(acc[3][3],ap,b1.y);
            ap = pk2(a1.x); fma2(acc[4][0],ap,b0.x); fma2(acc[4][1],ap,b0.y); fma2(acc[4][2],ap,b1.x); fma2(acc[4][3],ap,b1.y);
            ap = pk2(a1.y); fma2(acc[5][0],ap,b0.x); fma2(acc[5][1],ap,b0.y); fma2(acc[5][2],ap,b1.x); fma2(acc[5][3],ap,b1.y);
            ap = pk2(a1.z); fma2(acc[6][0],ap,b0.x); fma2(acc[6][1],ap,b0.y); fma2(acc[6][2],ap,b1.x); fma2(acc[6][3],ap,b1.y);
            ap = pk2(a1.w); fma2(acc[7][0],ap,b0.x); fma2(acc[7][1],ap,b0.y); fma2(acc[7][2],ap,b1.x); fma2(acc[7][3],ap,b1.y);
        }
        __syncthreads();
    }

    #pragma unroll
    for (int i = 0; i < 8; ++i) {
        int row = m0 + tm * 8 + i;
        #pragma unroll
        for (int p = 0; p < 4; ++p) {
            float2 v = up2(acc[i][p]);
            int col = n0 + tn * 8 + p * 2;
            if (EPI == 2) {
                int tt = row >> 6, bb = row & 63;
                float* o = C + ((size_t)(bb * TSTEPS + tt)) * VOCAB;
                if (col     < VOCAB) o[col]     = v.x + bias[col];
                if (col + 1 < VOCAB) o[col + 1] = v.y + bias[col + 1];
            } else {
                float r0 = v.x + bias[col], r1 = v.y + bias[col + 1];
                if (EPI == 1) { r0 = fmaxf(r0, 0.f); r1 = fmaxf(r1, 0.f); }
                *(float2*)&C[(size_t)row * N + col] = make_float2(r0, r1);
            }
        }
    }
}

// ------------------- small GEMM body: 64 x 64 tile, K-slice 64 --------------
// A is [64, 512] (g_h or g_x, lda=512). Writes raw partial (no bias).
__device__ __forceinline__ void sg64(const float* __restrict__ A,
                                     const float* __restrict__ Bp, int ldb,
                                     float* __restrict__ C, int ldc,
                                     int k0, int n0)
{
    __shared__ __align__(16) float As[64][64];
    __shared__ __align__(16) float Bs[64][64];
    const int tid = threadIdx.x;  // 256 threads
    {
        int a_m = tid & 63, a_kq = tid >> 6;           // 4 k-quarters
        #pragma unroll
        for (int i = 0; i < 4; ++i) {
            int kk = a_kq * 16 + i * 4;
            float4 v = *(const float4*)&A[a_m * 512 + k0 + kk];
            As[kk+0][a_m] = v.x; As[kk+1][a_m] = v.y;
            As[kk+2][a_m] = v.z; As[kk+3][a_m] = v.w;
        }
        int b_n4 = tid & 15, b_kr = tid >> 4;          // 16 k rows / pass
        #pragma unroll
        for (int p = 0; p < 4; ++p) {
            int kr = b_kr + p * 16;
            *(float4*)&Bs[kr][b_n4 * 4] =
                *(const float4*)&Bp[(size_t)(k0 + kr) * ldb + n0 + b_n4 * 4];
        }
    }
    __syncthreads();
    const int tm = tid >> 4, tn = tid & 15;
    unsigned long long acc[4][2] = {};
    #pragma unroll 16
    for (int kk = 0; kk < 64; ++kk) {
        float4 a = *(const float4*)&As[kk][tm*4];
        ulonglong2 b = *(const ulonglong2*)&Bs[kk][tn*4];
        unsigned long long ap;
        ap = pk2(a.x); fma2(acc[0][0],ap,b.x); fma2(acc[0][1],ap,b.y);
        ap = pk2(a.y); fma2(acc[1][0],ap,b.x); fma2(acc[1][1],ap,b.y);
        ap = pk2(a.z); fma2(acc[2][0],ap,b.x); fma2(acc[2][1],ap,b.y);
        ap = pk2(a.w); fma2(acc[3][0],ap,b.x); fma2(acc[3][1],ap,b.y);
    }
    #pragma unroll
    for (int r = 0; r < 4; ++r) {
        float2 v0 = up2(acc[r][0]), v1 = up2(acc[r][1]);
        float* c = &C[(size_t)(tm*4+r)*ldc + n0 + tn*4];
        c[0]=v0.x; c[1]=v0.y; c[2]=v1.x; c[3]=v1.y;
    }
}

// K1: partials of h @ [W2 | gru_rk].  grid (32, NSPLIT), 256 thr
__global__ __launch_bounds__(256)
void k_step1(const float* __restrict__ W2, const float* __restrict__ rk)
{
    int xb = blockIdx.x, sp = blockIdx.y;
    int k0 = sp * 64;
    if (xb < 8)
        sg64(g_h, W2, 512,  g_hW2p + sp * (B_SZ*UNITS),   512,  k0, xb * 64);
    else
        sg64(g_h, rk, 1536, g_ghp  + sp * (B_SZ*3*UNITS), 1536, k0, (xb - 8) * 64);
}

// K3a: partials of x @ gru_k.  grid (24, NSPLIT), 256 thr
__global__ __launch_bounds__(256)
void k_step3a(const float* __restrict__ gk)
{
    int xb = blockIdx.x, sp = blockIdx.y;
    sg64(g_x, gk, 1536, g_gxp + sp * (B_SZ*3*UNITS), 1536, sp * 64, xb * 64);
}

// K2: attention per batch element. grid 64, 512 thr
__global__ __launch_bounds__(512)
void k_attn(const float* __restrict__ W2_b, const float* __restrict__ V_W,
            const float* __restrict__ V_b,  const float* __restrict__ emb,
            const int* __restrict__ label, int t)
{
    __shared__ float s_hw2[512], s_vw[512], s_sc[64], s_ctx[2][256];
    const int b = blockIdx.x, tid = threadIdx.x;

    { // hW2 = sum of partials + bias; cache V_W
        float s = W2_b[tid];
        #pragma unroll
        for (int sp = 0; sp < NSPLIT; ++sp) s += g_hW2p[sp*(B_SZ*UNITS) + b*512 + tid];
        s_hw2[tid] = s;
        s_vw[tid] = V_W[tid];
    }
    __syncthreads();

    { // scores: warp w -> l in {4w..4w+3}
        int w = tid >> 5, lane = tid & 31;
        float vb = V_b[0];
        #pragma unroll
        for (int j = 0; j < 4; ++j) {
            int l = w * 4 + j;
            const float* fw = g_featW1 + (size_t)(b * 64 + l) * 512;
            float p = 0.f;
            #pragma unroll
            for (int i = 0; i < 16; ++i) {
                int u = lane + i * 32;
                p += s_vw[u] * fast_tanh(fw[u] + s_hw2[u]);
            }
            #pragma unroll
            for (int off = 16; off >= 1; off >>= 1)
                p += __shfl_xor_sync(0xffffffffu, p, off);
            if (lane == 0) s_sc[l] = p + vb;
        }
    }
    __syncthreads();

    if (tid < 32) { // softmax over 64
        float s0 = s_sc[tid], s1 = s_sc[tid + 32];
        float m = fmaxf(s0, s1);
        #pragma unroll
        for (int off = 16; off >= 1; off >>= 1)
            m = fmaxf(m, __shfl_xor_sync(0xffffffffu, m, off));
        float e0 = __expf(s0 - m), e1 = __expf(s1 - m);
        float sum = e0 + e1;
        #pragma unroll
        for (int off = 16; off >= 1; off >>= 1)
            sum += __shfl_xor_sync(0xffffffffu, sum, off);
        float inv = __fdividef(1.0f, sum);
        s_sc[tid] = e0 * inv; s_sc[tid + 32] = e1 * inv;
    }
    __syncthreads();

    { // ctx
        int u = tid & 255, half = tid >> 8;
        float c = 0.f;
        #pragma unroll 8
        for (int l = half * 32; l < half * 32 + 32; ++l)
            c += s_sc[l] * g_feat[(size_t)(b * 64 + l) * 256 + u];
        s_ctx[half][u] = c;
    }
    __syncthreads();

    if (tid < 256) {
        g_x[b * 512 + tid] = s_ctx[0][tid] + s_ctx[1][tid];
    } else {
        int u = tid - 256;
        int tok = (t == 0) ? 3 : label[b * TSTEPS + t - 1];
        g_x[b * 512 + 256 + u] = emb[(size_t)tok * 256 + u];
    }
}

// K3b: reduce partials + GRU gates + h_new. grid 128, 256 thr
__global__ __launch_bounds__(256)
void k_gates(const float* __restrict__ gb, int t)
{
    int idx = blockIdx.x * 256 + threadIdx.x;     // 0..32767
    int b = idx >> 9, u = idx & 511;
    float gxz = 0, gxr = 0, gxh = 0, ghz = 0, ghr = 0, ghh = 0;
    #pragma unroll
    for (int s = 0; s < NSPLIT; ++s) {
        int base = s * (B_SZ*3*UNITS) + b * 1536 + u;
        gxz += g_gxp[base]; gxr += g_gxp[base + 512]; gxh += g_gxp[base + 1024];
        ghz += g_ghp[base]; ghr += g_ghp[base + 512]; ghh += g_ghp[base + 1024];
    }
    float xz = gxz + gb[u],        xr = gxr + gb[512 + u],  xh = gxh + gb[1024 + u];
    float hz = ghz + gb[1536 + u], hr = ghr + gb[2048 + u], hh = ghh + gb[2560 + u];
    float z = fast_sigm(xz + hz);
    float r = fast_sigm(xr + hr);
    float n = fast_tanh(xh + r * hh);
    float hold = g_h[idx];
    float hn = z * hold + (1.0f - z) * n;
    g_h[idx] = hn;
    g_H[((size_t)t * 64 + b) * 512 + u] = hn;
}

// misc
__global__ void k_zero_h() {
    int i = blockIdx.x * 256 + threadIdx.x;
    if (i < B_SZ * UNITS) g_h[i] = 0.f;
}
__global__ void k_pad_fc2(const float* __restrict__ W) {
    int r = blockIdx.y;
    int c = blockIdx.x * 256 + threadIdx.x;
    if (c < PADN)
        g_fc2Wp[(size_t)r * PADN + c] = (c < VOCAB) ? W[(size_t)r * VOCAB + c] : 0.f;
}
__global__ void k_labels(const int* __restrict__ label, float* __restrict__ out) {
    int i = blockIdx.x * 256 + threadIdx.x;
    if (i < B_SZ * TSTEPS) out[PROBA_ELEMS + i] = (float)label[i];
}

// ---------------------------------------------------------------------------
extern "C" void kernel_launch(void* const* d_in, const int* in_sizes, int n_in,
                              void* d_out, int out_size)
{
    const float* data    = (const float*)d_in[0];
    const int*   label   = (const int*)  d_in[1];
    const float* dense_W = (const float*)d_in[2];
    const float* dense_b = (const float*)d_in[3];
    const float* emb     = (const float*)d_in[4];
    const float* gru_k   = (const float*)d_in[5];
    const float* gru_rk  = (const float*)d_in[6];
    const float* gru_b   = (const float*)d_in[7];
    const float* fc1_W   = (const float*)d_in[8];
    const float* fc1_b   = (const float*)d_in[9];
    const float* fc2_W   = (const float*)d_in[10];
    const float* fc2_b   = (const float*)d_in[11];
    const float* W1      = (const float*)d_in[12];
    const float* W1_b    = (const float*)d_in[13];
    const float* W2      = (const float*)d_in[14];
    const float* W2_b    = (const float*)d_in[15];
    const float* V_W     = (const float*)d_in[16];
    const float* V_b     = (const float*)d_in[17];
    float* out = (float*)d_out;

    float *feat, *featW1, *H, *F1, *fc2p;
    cudaGetSymbolAddress((void**)&feat,   g_feat);
    cudaGetSymbolAddress((void**)&featW1, g_featW1);
    cudaGetSymbolAddress((void**)&H,      g_H);
    cudaGetSymbolAddress((void**)&F1,     g_F1);
    cudaGetSymbolAddress((void**)&fc2p,   g_fc2Wp);

    k_zero_h<<<128, 256>>>();
    k_pad_fc2<<<dim3((PADN + 255) / 256, UNITS), 256>>>(fc2_W);

    // feat = relu(data @ dense_W + b)      [4096,2048]x[2048,256]
    sgemm<1><<<dim3(EMB/64, ML/128), 128>>>(data, dense_W, dense_b, feat,
                                            ML, EMB, FEATD, EMB);
    // featW1 = feat @ W1 + b               [4096,256]x[256,512]
    sgemm<0><<<dim3(UNITS/64, ML/128), 128>>>(feat, W1, W1_b, featW1,
                                              ML, UNITS, EMB, UNITS);

    for (int t = 0; t < TSTEPS; ++t) {
        k_step1<<<dim3(32, NSPLIT), 256>>>(W2, gru_rk);
        k_attn <<<B_SZ, 512>>>(W2_b, V_W, V_b, emb, label, t);
        k_step3a<<<dim3(24, NSPLIT), 256>>>(gru_k);
        k_gates<<<128, 256>>>(gru_b, t);
    }

    // F1 = H @ fc1_W + b                   [3328,512]x[512,512]
    sgemm<0><<<dim3(UNITS/64, MTB/128), 128>>>(H, fc1_W, fc1_b, F1,
                                               MTB, UNITS, UNITS, UNITS);
    // proba = F1 @ fc2Wp + b  (remap t,b -> b,t; guard col < VOCAB)
    sgemm<2><<<dim3(PADN/64, MTB/128), 128>>>(F1, fc2p, fc2_b, out,
                                              MTB, PADN, UNITS, PADN);

    if ((size_t)out_size >= PROBA_ELEMS + (size_t)B_SZ * TSTEPS)
        k_labels<<<(B_SZ * TSTEPS + 255) / 256, 256>>>(label, out);
}

// round 6
// speedup vs baseline: 1.2441x; 1.2441x over previous
#include <cuda_runtime.h>
#include <cuda_bf16.h>
#include <cstdint>

// ---------------------------------------------------------------------------
// AutoEncoder_32143535244000: Bahdanau-attention GRU decoder
// B=64, L=64, F=2048, EMB=256, UNITS=512, VOCAB=10001, T=52
// fc2 (3328x10001x512) on mma.sync bf16 split (hi/lo) — portable HMMA path.
// R4 fix: scalar epilogue stores (VOCAB odd -> float2 store misaligns on odd rows).
// ---------------------------------------------------------------------------

#define B_SZ   64
#define L_SZ   64
#define FEATD  2048
#define EMB    256
#define UNITS  512
#define VOCAB  10001
#define TSTEPS 52
#define ML     (B_SZ*L_SZ)             // 4096
#define MTB    (TSTEPS*B_SZ)           // 3328 = 26*128
#define NPAD   10112                   // 79*128
#define NSPLIT 8
#define PROBA_ELEMS ((size_t)B_SZ*TSTEPS*VOCAB)

// ------------------------------- scratch -----------------------------------
__device__ float g_feat  [ML*EMB];
__device__ float g_featW1[ML*UNITS];
__device__ float g_h     [B_SZ*UNITS];
__device__ float g_x     [B_SZ*2*EMB];
__device__ float g_hW2p  [NSPLIT*B_SZ*UNITS];
__device__ float g_ghp   [NSPLIT*B_SZ*3*UNITS];
__device__ float g_gxp   [NSPLIT*B_SZ*3*UNITS];
__device__ float g_H     [MTB*UNITS];
__device__ float g_F1    [MTB*UNITS];
__device__ __align__(16) __nv_bfloat16 g_F1h[MTB*UNITS];
__device__ __align__(16) __nv_bfloat16 g_F1l[MTB*UNITS];
__device__ __align__(16) __nv_bfloat16 g_Wth[(size_t)NPAD*UNITS];
__device__ __align__(16) __nv_bfloat16 g_Wtl[(size_t)NPAD*UNITS];

// ----------------------------- fp32 helpers --------------------------------
__device__ __forceinline__ unsigned long long pk2(float x) {
    unsigned long long r;
    unsigned int xi = __float_as_uint(x);
    asm("mov.b64 %0, {%1, %1};" : "=l"(r) : "r"(xi));
    return r;
}
__device__ __forceinline__ void fma2(unsigned long long &d,
                                     unsigned long long a, unsigned long long b) {
    asm("fma.rn.f32x2 %0, %1, %2, %0;" : "+l"(d) : "l"(a), "l"(b));
}
__device__ __forceinline__ float2 up2(unsigned long long v) {
    unsigned int lo, hi;
    asm("mov.b64 {%0, %1}, %2;" : "=r"(lo), "=r"(hi) : "l"(v));
    return make_float2(__uint_as_float(lo), __uint_as_float(hi));
}
__device__ __forceinline__ float fast_tanh(float x) {
    float e = __expf(2.0f * x);
    return 1.0f - __fdividef(2.0f, e + 1.0f);
}
__device__ __forceinline__ float fast_sigm(float x) {
    return __fdividef(1.0f, 1.0f + __expf(-x));
}
__device__ __forceinline__ uint32_t smem_u32(const void* p) {
    uint32_t a;
    asm("{ .reg .u64 t; cvta.to.shared.u64 t, %1; cvt.u32.u64 %0, t; }"
        : "=r"(a) : "l"(p));
    return a;
}

// ---------------------------- HMMA helpers ---------------------------------
__device__ __forceinline__ void ldsm4(uint32_t* r, uint32_t a) {
    asm volatile("ldmatrix.sync.aligned.m8n8.x4.shared.b16 {%0,%1,%2,%3}, [%4];"
        : "=r"(r[0]), "=r"(r[1]), "=r"(r[2]), "=r"(r[3]) : "r"(a));
}
__device__ __forceinline__ void mma16816(float* c, const uint32_t* a,
                                         const uint32_t* b) {
    asm volatile("mma.sync.aligned.m16n8k16.row.col.f32.bf16.bf16.f32 "
        "{%0,%1,%2,%3}, {%4,%5,%6,%7}, {%8,%9}, {%0,%1,%2,%3};"
        : "+f"(c[0]), "+f"(c[1]), "+f"(c[2]), "+f"(c[3])
        : "r"(a[0]), "r"(a[1]), "r"(a[2]), "r"(a[3]), "r"(b[0]), "r"(b[1]));
}
__device__ __forceinline__ void cpa16(uint32_t s, const void* g) {
    asm volatile("cp.async.cg.shared.global [%0], [%1], 16;" :: "r"(s), "l"(g));
}
#define CP_COMMIT() asm volatile("cp.async.commit_group;" ::: "memory")
template<int N> __device__ __forceinline__ void cp_wait() {
    asm volatile("cp.async.wait_group %0;" :: "n"(N) : "memory");
}

// ------------------------- big SGEMM (f32x2) --------------------------------
template<int EPI>   // 0: +bias | 1: +bias, relu
__global__ __launch_bounds__(128)
void sgemm(const float* __restrict__ A, const float* __restrict__ B,
           const float* __restrict__ bias, float* __restrict__ C,
           int M, int N, int K, int ldb)
{
    __shared__ __align__(16) float As[16][128];
    __shared__ __align__(16) float Bs[16][64];
    const int tid = threadIdx.x;
    const int m0 = blockIdx.y * 128, n0 = blockIdx.x * 64;
    const int a_kf = tid & 3,  a_r  = tid >> 2;
    const int b_nf = tid & 15, b_kr = tid >> 4;
    const int tm = tid >> 3, tn = tid & 7;
    unsigned long long acc[8][4] = {};

    for (int k0 = 0; k0 < K; k0 += 16) {
        #pragma unroll
        for (int p = 0; p < 4; ++p) {
            int row = a_r + p * 32;
            float4 v = *(const float4*)&A[(size_t)(m0 + row) * K + k0 + a_kf * 4];
            As[a_kf*4+0][row] = v.x; As[a_kf*4+1][row] = v.y;
            As[a_kf*4+2][row] = v.z; As[a_kf*4+3][row] = v.w;
        }
        #pragma unroll
        for (int p = 0; p < 2; ++p) {
            int kr = b_kr + p * 8;
            *(float4*)&Bs[kr][b_nf*4] =
                *(const float4*)&B[(size_t)(k0 + kr) * ldb + n0 + b_nf * 4];
        }
        __syncthreads();
        #pragma unroll
        for (int kk = 0; kk < 16; ++kk) {
            float4 a0 = *(const float4*)&As[kk][tm*8];
            float4 a1 = *(const float4*)&As[kk][tm*8+4];
            ulonglong2 b0 = *(const ulonglong2*)&Bs[kk][tn*8];
            ulonglong2 b1 = *(const ulonglong2*)&Bs[kk][tn*8+4];
            unsigned long long ap;
            ap = pk2(a0.x); fma2(acc[0][0],ap,b0.x); fma2(acc[0][1],ap,b0.y); fma2(acc[0][2],ap,b1.x); fma2(acc[0][3],ap,b1.y);
            ap = pk2(a0.y); fma2(acc[1][0],ap,b0.x); fma2(acc[1][1],ap,b0.y); fma2(acc[1][2],ap,b1.x); fma2(acc[1][3],ap,b1.y);
            ap = pk2(a0.z); fma2(acc[2][0],ap,b0.x); fma2(acc[2][1],ap,b0.y); fma2(acc[2][2],ap,b1.x); fma2(acc[2][3],ap,b1.y);
            ap = pk2(a0.w); fma2(acc[3][0],ap,b0.x); fma2(acc[3][1],ap,b0.y); fma2(acc[3][2],ap,b1.x); fma2(acc[3][3],ap,b1.y);
            ap = pk2(a1.x); fma2(acc[4][0],ap,b0.x); fma2(acc[4][1],ap,b0.y); fma2(acc[4][2],ap,b1.x); fma2(acc[4][3],ap,b1.y);
            ap = pk2(a1.y); fma2(acc[5][0],ap,b0.x); fma2(acc[5][1],ap,b0.y); fma2(acc[5][2],ap,b1.x); fma2(acc[5][3],ap,b1.y);
            ap = pk2(a1.z); fma2(acc[6][0],ap,b0.x); fma2(acc[6][1],ap,b0.y); fma2(acc[6][2],ap,b1.x); fma2(acc[6][3],ap,b1.y);
            ap = pk2(a1.w); fma2(acc[7][0],ap,b0.x); fma2(acc[7][1],ap,b0.y); fma2(acc[7][2],ap,b1.x); fma2(acc[7][3],ap,b1.y);
        }
        __syncthreads();
    }
    #pragma unroll
    for (int i = 0; i < 8; ++i) {
        int row = m0 + tm * 8 + i;
        #pragma unroll
        for (int p = 0; p < 4; ++p) {
            float2 v = up2(acc[i][p]);
            int col = n0 + tn * 8 + p * 2;
            float r0 = v.x + bias[col], r1 = v.y + bias[col + 1];
            if (EPI == 1) { r0 = fmaxf(r0, 0.f); r1 = fmaxf(r1, 0.f); }
            *(float2*)&C[(size_t)row * N + col] = make_float2(r0, r1);
        }
    }
}

// --------------- fc2: HMMA split-bf16 GEMM D = F1 @ Wt^T --------------------
// grid (26 m, 79 n), 256 thr, tile 128x128, K=512 in 16 k32 stages
#define ROWB   80                      // padded bf16 row: 32 elems (64B) + 16B pad
#define ARR_B  (128*ROWB)              // 10240 B per operand array
#define STG_B  (4*ARR_B)               // 40960 B per stage
#define FC2_DSMEM (2*STG_B)            // 81920 B

__device__ __forceinline__ void fc2_load_stage(uint32_t sb, int tid,
                                               int m0, int n0, int k0)
{
    int c0 = tid * 2;
    #pragma unroll
    for (int a = 0; a < 4; ++a) {
        const __nv_bfloat16* src = (a == 0) ? g_F1h : (a == 1) ? g_F1l
                                 : (a == 2) ? g_Wth : g_Wtl;
        int rb = (a < 2) ? m0 : n0;
        #pragma unroll
        for (int u = 0; u < 2; ++u) {
            int c = c0 + u, r = c >> 2, q = c & 3;
            cpa16(sb + a * ARR_B + r * ROWB + q * 16,
                  src + (size_t)(rb + r) * UNITS + k0 + q * 8);
        }
    }
}

__global__ __launch_bounds__(256)
void fc2_mma(const float* __restrict__ bias, float* __restrict__ out)
{
    extern __shared__ __align__(16) unsigned char smem[];
    const uint32_t sbase = smem_u32(smem);
    const int tid = threadIdx.x, lane = tid & 31, wid = tid >> 5;
    const int wm = wid & 3, wn = wid >> 2;
    const int m0 = blockIdx.x * 128, n0 = blockIdx.y * 128;

    float acc[2][8][4];
    #pragma unroll
    for (int i = 0; i < 2; ++i)
        #pragma unroll
        for (int j = 0; j < 8; ++j)
            #pragma unroll
            for (int q = 0; q < 4; ++q) acc[i][j][q] = 0.f;

    const int a_row = wm * 32 + ((lane >> 3) & 1) * 8 + (lane & 7);
    const uint32_t a_koff = (lane >> 4) * 16;
    const int b_row = wn * 64 + (lane >> 4) * 8 + (lane & 7);
    const uint32_t b_koff = ((lane >> 3) & 1) * 16;

    fc2_load_stage(sbase, tid, m0, n0, 0);
    CP_COMMIT();

    for (int ks = 0; ks < 16; ++ks) {
        if (ks + 1 < 16) {
            fc2_load_stage(sbase + ((ks + 1) & 1) * STG_B, tid, m0, n0,
                           (ks + 1) * 32);
            CP_COMMIT();
            cp_wait<1>();
        } else {
            cp_wait<0>();
        }
        __syncthreads();

        const uint32_t sAh = sbase + (ks & 1) * STG_B;
        const uint32_t sAl = sAh + ARR_B;
        const uint32_t sBh = sAh + 2 * ARR_B;
        const uint32_t sBl = sAh + 3 * ARR_B;

        #pragma unroll
        for (int kk = 0; kk < 2; ++kk) {
            uint32_t ah[2][4], al[2][4];
            #pragma unroll
            for (int i = 0; i < 2; ++i) {
                uint32_t ao = (uint32_t)(a_row + i * 16) * ROWB + a_koff + kk * 32;
                ldsm4(ah[i], sAh + ao);
                ldsm4(al[i], sAl + ao);
            }
            uint32_t bh[4][4], bl[4][4];
            #pragma unroll
            for (int jj = 0; jj < 4; ++jj) {
                uint32_t bo = (uint32_t)(b_row + jj * 16) * ROWB + b_koff + kk * 32;
                ldsm4(bh[jj], sBh + bo);
                ldsm4(bl[jj], sBl + bo);
            }
            #pragma unroll
            for (int i = 0; i < 2; ++i)
                #pragma unroll
                for (int j = 0; j < 8; ++j) {
                    const uint32_t* ph = bh[j >> 1] + (j & 1) * 2;
                    const uint32_t* pl = bl[j >> 1] + (j & 1) * 2;
                    mma16816(acc[i][j], ah[i], ph);
                    mma16816(acc[i][j], ah[i], pl);
                    mma16816(acc[i][j], al[i], ph);
                }
        }
        __syncthreads();
    }

    // epilogue: remap row t*64+b -> (b*52+t), add bias; SCALAR stores
    // (VOCAB=10001 is odd -> odd rows are only 4B-aligned; float2 would fault)
    #pragma unroll
    for (int i = 0; i < 2; ++i) {
        #pragma unroll
        for (int half = 0; half < 2; ++half) {
            int row = m0 + wm * 32 + i * 16 + (lane >> 2) + half * 8;
            int tt = row >> 6, bb = row & 63;
            float* o = out + (size_t)(bb * TSTEPS + tt) * VOCAB;
            #pragma unroll
            for (int j = 0; j < 8; ++j) {
                int col = n0 + wn * 64 + j * 8 + (lane & 3) * 2;
                float v0 = acc[i][j][half * 2];
                float v1 = acc[i][j][half * 2 + 1];
                if (col < VOCAB)     o[col]     = v0 + __ldg(&bias[col]);
                if (col + 1 < VOCAB) o[col + 1] = v1 + __ldg(&bias[col + 1]);
            }
        }
    }
}

// --------------------- prep: transpose + bf16-split fc2 W -------------------
__global__ __launch_bounds__(256)
void k_prep_w(const float* __restrict__ W)
{
    __shared__ float s[32][33];
    int n0 = blockIdx.x * 32, k0 = blockIdx.y * 32;
    int tx = threadIdx.x & 31, ty = threadIdx.x >> 5;
    #pragma unroll
    for (int p = 0; p < 4; ++p) {
        int k = ty + p * 8, n = n0 + tx;
        s[k][tx] = (n < VOCAB) ? W[(size_t)(k0 + k) * VOCAB + n] : 0.f;
    }
    __syncthreads();
    #pragma unroll
    for (int p = 0; p < 4; ++p) {
        int nl = ty + p * 8;
        size_t oi = (size_t)(n0 + nl) * UNITS + (k0 + tx);
        float v = s[tx][nl];
        __nv_bfloat16 hi = __float2bfloat16(v);
        g_Wth[oi] = hi;
        g_Wtl[oi] = __float2bfloat16(v - __bfloat162float(hi));
    }
}

__global__ __launch_bounds__(256)
void k_split_f1()
{
    int i = blockIdx.x * 256 + threadIdx.x;
    if (i < MTB * UNITS) {
        float v = g_F1[i];
        __nv_bfloat16 hi = __float2bfloat16(v);
        g_F1h[i] = hi;
        g_F1l[i] = __float2bfloat16(v - __bfloat162float(hi));
    }
}

// ------------------- small GEMM body: 64 x 64 tile, K-slice 64 --------------
__device__ __forceinline__ void sg64(const float* __restrict__ A,
                                     const float* __restrict__ Bp, int ldb,
                                     float* __restrict__ C, int ldc,
                                     int k0, int n0)
{
    __shared__ __align__(16) float As[64][64];
    __shared__ __align__(16) float Bs[64][64];
    const int tid = threadIdx.x;
    {
        int a_m = tid & 63, a_kq = tid >> 6;
        #pragma unroll
        for (int i = 0; i < 4; ++i) {
            int kk = a_kq * 16 + i * 4;
            float4 v = *(const float4*)&A[a_m * 512 + k0 + kk];
            As[kk+0][a_m] = v.x; As[kk+1][a_m] = v.y;
            As[kk+2][a_m] = v.z; As[kk+3][a_m] = v.w;
        }
        int b_n4 = tid & 15, b_kr = tid >> 4;
        #pragma unroll
        for (int p = 0; p < 4; ++p) {
            int kr = b_kr + p * 16;
            *(float4*)&Bs[kr][b_n4 * 4] =
                *(const float4*)&Bp[(size_t)(k0 + kr) * ldb + n0 + b_n4 * 4];
        }
    }
    __syncthreads();
    const int tm = tid >> 4, tn = tid & 15;
    unsigned long long acc[4][2] = {};
    #pragma unroll 16
    for (int kk = 0; kk < 64; ++kk) {
        float4 a = *(const float4*)&As[kk][tm*4];
        ulonglong2 b = *(const ulonglong2*)&Bs[kk][tn*4];
        unsigned long long ap;
        ap = pk2(a.x); fma2(acc[0][0],ap,b.x); fma2(acc[0][1],ap,b.y);
        ap = pk2(a.y); fma2(acc[1][0],ap,b.x); fma2(acc[1][1],ap,b.y);
        ap = pk2(a.z); fma2(acc[2][0],ap,b.x); fma2(acc[2][1],ap,b.y);
        ap = pk2(a.w); fma2(acc[3][0],ap,b.x); fma2(acc[3][1],ap,b.y);
    }
    #pragma unroll
    for (int r = 0; r < 4; ++r) {
        float2 v0 = up2(acc[r][0]), v1 = up2(acc[r][1]);
        float* c = &C[(size_t)(tm*4+r)*ldc + n0 + tn*4];
        c[0]=v0.x; c[1]=v0.y; c[2]=v1.x; c[3]=v1.y;
    }
}

__global__ __launch_bounds__(256)
void k_step1(const float* __restrict__ W2, const float* __restrict__ rk)
{
    int xb = blockIdx.x, sp = blockIdx.y;
    int k0 = sp * 64;
    if (xb < 8)
        sg64(g_h, W2, 512,  g_hW2p + sp * (B_SZ*UNITS),   512,  k0, xb * 64);
    else
        sg64(g_h, rk, 1536, g_ghp  + sp * (B_SZ*3*UNITS), 1536, k0, (xb - 8) * 64);
}

__global__ __launch_bounds__(256)
void k_step3a(const float* __restrict__ gk)
{
    int xb = blockIdx.x, sp = blockIdx.y;
    sg64(g_x, gk, 1536, g_gxp + sp * (B_SZ*3*UNITS), 1536, sp * 64, xb * 64);
}

__global__ __launch_bounds__(512)
void k_attn(const float* __restrict__ W2_b, const float* __restrict__ V_W,
            const float* __restrict__ V_b,  const float* __restrict__ emb,
            const int* __restrict__ label, int t)
{
    __shared__ float s_hw2[512], s_vw[512], s_sc[64], s_ctx[2][256];
    const int b = blockIdx.x, tid = threadIdx.x;
    {
        float s = W2_b[tid];
        #pragma unroll
        for (int sp = 0; sp < NSPLIT; ++sp) s += g_hW2p[sp*(B_SZ*UNITS) + b*512 + tid];
        s_hw2[tid] = s;
        s_vw[tid] = V_W[tid];
    }
    __syncthreads();
    {
        int w = tid >> 5, lane = tid & 31;
        float vb = V_b[0];
        #pragma unroll
        for (int j = 0; j < 4; ++j) {
            int l = w * 4 + j;
            const float* fw = g_featW1 + (size_t)(b * 64 + l) * 512;
            float p = 0.f;
            #pragma unroll
            for (int i = 0; i < 16; ++i) {
                int u = lane + i * 32;
                p += s_vw[u] * fast_tanh(fw[u] + s_hw2[u]);
            }
            #pragma unroll
            for (int off = 16; off >= 1; off >>= 1)
                p += __shfl_xor_sync(0xffffffffu, p, off);
            if (lane == 0) s_sc[l] = p + vb;
        }
    }
    __syncthreads();
    if (tid < 32) {
        float s0 = s_sc[tid], s1 = s_sc[tid + 32];
        float m = fmaxf(s0, s1);
        #pragma unroll
        for (int off = 16; off >= 1; off >>= 1)
            m = fmaxf(m, __shfl_xor_sync(0xffffffffu, m, off));
        float e0 = __expf(s0 - m), e1 = __expf(s1 - m);
        float sum = e0 + e1;
        #pragma unroll
        for (int off = 16; off >= 1; off >>= 1)
            sum += __shfl_xor_sync(0xffffffffu, sum, off);
        float inv = __fdividef(1.0f, sum);
        s_sc[tid] = e0 * inv; s_sc[tid + 32] = e1 * inv;
    }
    __syncthreads();
    {
        int u = tid & 255, half = tid >> 8;
        float c = 0.f;
        #pragma unroll 8
        for (int l = half * 32; l < half * 32 + 32; ++l)
            c += s_sc[l] * g_feat[(size_t)(b * 64 + l) * 256 + u];
        s_ctx[half][u] = c;
    }
    __syncthreads();
    if (tid < 256) {
        g_x[b * 512 + tid] = s_ctx[0][tid] + s_ctx[1][tid];
    } else {
        int u = tid - 256;
        int tok = (t == 0) ? 3 : label[b * TSTEPS + t - 1];
        g_x[b * 512 + 256 + u] = emb[(size_t)tok * 256 + u];
    }
}

__global__ __launch_bounds__(256)
void k_gates(const float* __restrict__ gb, int t)
{
    int idx = blockIdx.x * 256 + threadIdx.x;
    int b = idx >> 9, u = idx & 511;
    float gxz = 0, gxr = 0, gxh = 0, ghz = 0, ghr = 0, ghh = 0;
    #pragma unroll
    for (int s = 0; s < NSPLIT; ++s) {
        int base = s * (B_SZ*3*UNITS) + b * 1536 + u;
        gxz += g_gxp[base]; gxr += g_gxp[base + 512]; gxh += g_gxp[base + 1024];
        ghz += g_ghp[base]; ghr += g_ghp[base + 512]; ghh += g_ghp[base + 1024];
    }
    float xz = gxz + gb[u],        xr = gxr + gb[512 + u],  xh = gxh + gb[1024 + u];
    float hz = ghz + gb[1536 + u], hr = ghr + gb[2048 + u], hh = ghh + gb[2560 + u];
    float z = fast_sigm(xz + hz);
    float r = fast_sigm(xr + hr);
    float n = fast_tanh(xh + r * hh);
    float hold = g_h[idx];
    float hn = z * hold + (1.0f - z) * n;
    g_h[idx] = hn;
    g_H[((size_t)t * 64 + b) * 512 + u] = hn;
}

__global__ void k_zero_h() {
    int i = blockIdx.x * 256 + threadIdx.x;
    if (i < B_SZ * UNITS) g_h[i] = 0.f;
}
__global__ void k_labels(const int* __restrict__ label, float* __restrict__ out) {
    int i = blockIdx.x * 256 + threadIdx.x;
    if (i < B_SZ * TSTEPS) out[PROBA_ELEMS + i] = (float)label[i];
}

// ---------------------------------------------------------------------------
extern "C" void kernel_launch(void* const* d_in, const int* in_sizes, int n_in,
                              void* d_out, int out_size)
{
    const float* data    = (const float*)d_in[0];
    const int*   label   = (const int*)  d_in[1];
    const float* dense_W = (const float*)d_in[2];
    const float* dense_b = (const float*)d_in[3];
    const float* emb     = (const float*)d_in[4];
    const float* gru_k   = (const float*)d_in[5];
    const float* gru_rk  = (const float*)d_in[6];
    const float* gru_b   = (const float*)d_in[7];
    const float* fc1_W   = (const float*)d_in[8];
    const float* fc1_b   = (const float*)d_in[9];
    const float* fc2_W   = (const float*)d_in[10];
    const float* fc2_b   = (const float*)d_in[11];
    const float* W1      = (const float*)d_in[12];
    const float* W1_b    = (const float*)d_in[13];
    const float* W2      = (const float*)d_in[14];
    const float* W2_b    = (const float*)d_in[15];
    const float* V_W     = (const float*)d_in[16];
    const float* V_b     = (const float*)d_in[17];
    float* out = (float*)d_out;

    float *feat, *featW1, *H, *F1;
    cudaGetSymbolAddress((void**)&feat,   g_feat);
    cudaGetSymbolAddress((void**)&featW1, g_featW1);
    cudaGetSymbolAddress((void**)&H,      g_H);
    cudaGetSymbolAddress((void**)&F1,     g_F1);

    cudaFuncSetAttribute(fc2_mma, cudaFuncAttributeMaxDynamicSharedMemorySize,
                         FC2_DSMEM);

    k_zero_h<<<128, 256>>>();
    k_prep_w<<<dim3(NPAD/32, UNITS/32), 256>>>(fc2_W);

    sgemm<1><<<dim3(EMB/64, ML/128), 128>>>(data, dense_W, dense_b, feat,
                                            ML, EMB, FEATD, EMB);
    sgemm<0><<<dim3(UNITS/64, ML/128), 128>>>(feat, W1, W1_b, featW1,
                                              ML, UNITS, EMB, UNITS);

    for (int t = 0; t < TSTEPS; ++t) {
        k_step1<<<dim3(32, NSPLIT), 256>>>(W2, gru_rk);
        k_attn <<<B_SZ, 512>>>(W2_b, V_W, V_b, emb, label, t);
        k_step3a<<<dim3(24, NSPLIT), 256>>>(gru_k);
        k_gates<<<128, 256>>>(gru_b, t);
    }

    sgemm<0><<<dim3(UNITS/64, MTB/128), 128>>>(H, fc1_W, fc1_b, F1,
                                               MTB, UNITS, UNITS, UNITS);
    k_split_f1<<<(MTB*UNITS + 255)/256, 256>>>();

    fc2_mma<<<dim3(MTB/128, NPAD/128), 256, FC2_DSMEM>>>(fc2_b, out);

    if ((size_t)out_size >= PROBA_ELEMS + (size_t)B_SZ * TSTEPS)
        k_labels<<<(B_SZ * TSTEPS + 255) / 256, 256>>>(label, out);
}

// round 7
// speedup vs baseline: 1.2453x; 1.0009x over previous
#include <cuda_runtime.h>
#include <cuda_bf16.h>
#include <cstdint>

// ---------------------------------------------------------------------------
// AutoEncoder_32143535244000: Bahdanau-attention GRU decoder
// B=64, L=64, F=2048, EMB=256, UNITS=512, VOCAB=10001, T=52
// fc2 (3328x10001x512) on mma.sync bf16 split (hi/lo) — portable HMMA path.
// R4 fix: scalar epilogue stores (VOCAB odd -> float2 store misaligns on odd rows).
// ---------------------------------------------------------------------------

#define B_SZ   64
#define L_SZ   64
#define FEATD  2048
#define EMB    256
#define UNITS  512
#define VOCAB  10001
#define TSTEPS 52
#define ML     (B_SZ*L_SZ)             // 4096
#define MTB    (TSTEPS*B_SZ)           // 3328 = 26*128
#define NPAD   10112                   // 79*128
#define NSPLIT 8
#define PROBA_ELEMS ((size_t)B_SZ*TSTEPS*VOCAB)

// ------------------------------- scratch -----------------------------------
__device__ float g_feat  [ML*EMB];
__device__ float g_featW1[ML*UNITS];
__device__ float g_h     [B_SZ*UNITS];
__device__ float g_x     [B_SZ*2*EMB];
__device__ float g_hW2p  [NSPLIT*B_SZ*UNITS];
__device__ float g_ghp   [NSPLIT*B_SZ*3*UNITS];
__device__ float g_gxp   [NSPLIT*B_SZ*3*UNITS];
__device__ float g_H     [MTB*UNITS];
__device__ float g_F1    [MTB*UNITS];
__device__ __align__(16) __nv_bfloat16 g_F1h[MTB*UNITS];
__device__ __align__(16) __nv_bfloat16 g_F1l[MTB*UNITS];
__device__ __align__(16) __nv_bfloat16 g_Wth[(size_t)NPAD*UNITS];
__device__ __align__(16) __nv_bfloat16 g_Wtl[(size_t)NPAD*UNITS];

// ----------------------------- fp32 helpers --------------------------------
__device__ __forceinline__ unsigned long long pk2(float x) {
    unsigned long long r;
    unsigned int xi = __float_as_uint(x);
    asm("mov.b64 %0, {%1, %1};" : "=l"(r) : "r"(xi));
    return r;
}
__device__ __forceinline__ void fma2(unsigned long long &d,
                                     unsigned long long a, unsigned long long b) {
    asm("fma.rn.f32x2 %0, %1, %2, %0;" : "+l"(d) : "l"(a), "l"(b));
}
__device__ __forceinline__ float2 up2(unsigned long long v) {
    unsigned int lo, hi;
    asm("mov.b64 {%0, %1}, %2;" : "=r"(lo), "=r"(hi) : "l"(v));
    return make_float2(__uint_as_float(lo), __uint_as_float(hi));
}
__device__ __forceinline__ float fast_tanh(float x) {
    float e = __expf(2.0f * x);
    return 1.0f - __fdividef(2.0f, e + 1.0f);
}
__device__ __forceinline__ float fast_sigm(float x) {
    return __fdividef(1.0f, 1.0f + __expf(-x));
}
__device__ __forceinline__ uint32_t smem_u32(const void* p) {
    uint32_t a;
    asm("{ .reg .u64 t; cvta.to.shared.u64 t, %1; cvt.u32.u64 %0, t; }"
        : "=r"(a) : "l"(p));
    return a;
}

// ---------------------------- HMMA helpers ---------------------------------
__device__ __forceinline__ void ldsm4(uint32_t* r, uint32_t a) {
    asm volatile("ldmatrix.sync.aligned.m8n8.x4.shared.b16 {%0,%1,%2,%3}, [%4];"
        : "=r"(r[0]), "=r"(r[1]), "=r"(r[2]), "=r"(r[3]) : "r"(a));
}
__device__ __forceinline__ void mma16816(float* c, const uint32_t* a,
                                         const uint32_t* b) {
    asm volatile("mma.sync.aligned.m16n8k16.row.col.f32.bf16.bf16.f32 "
        "{%0,%1,%2,%3}, {%4,%5,%6,%7}, {%8,%9}, {%0,%1,%2,%3};"
        : "+f"(c[0]), "+f"(c[1]), "+f"(c[2]), "+f"(c[3])
        : "r"(a[0]), "r"(a[1]), "r"(a[2]), "r"(a[3]), "r"(b[0]), "r"(b[1]));
}
__device__ __forceinline__ void cpa16(uint32_t s, const void* g) {
    asm volatile("cp.async.cg.shared.global [%0], [%1], 16;" :: "r"(s), "l"(g));
}
#define CP_COMMIT() asm volatile("cp.async.commit_group;" ::: "memory")
template<int N> __device__ __forceinline__ void cp_wait() {
    asm volatile("cp.async.wait_group %0;" :: "n"(N) : "memory");
}

// ------------------------- big SGEMM (f32x2) --------------------------------
template<int EPI>   // 0: +bias | 1: +bias, relu
__global__ __launch_bounds__(128)
void sgemm(const float* __restrict__ A, const float* __restrict__ B,
           const float* __restrict__ bias, float* __restrict__ C,
           int M, int N, int K, int ldb)
{
    __shared__ __align__(16) float As[16][128];
    __shared__ __align__(16) float Bs[16][64];
    const int tid = threadIdx.x;
    const int m0 = blockIdx.y * 128, n0 = blockIdx.x * 64;
    const int a_kf = tid & 3,  a_r  = tid >> 2;
    const int b_nf = tid & 15, b_kr = tid >> 4;
    const int tm = tid >> 3, tn = tid & 7;
    unsigned long long acc[8][4] = {};

    for (int k0 = 0; k0 < K; k0 += 16) {
        #pragma unroll
        for (int p = 0; p < 4; ++p) {
            int row = a_r + p * 32;
            float4 v = *(const float4*)&A[(size_t)(m0 + row) * K + k0 + a_kf * 4];
            As[a_kf*4+0][row] = v.x; As[a_kf*4+1][row] = v.y;
            As[a_kf*4+2][row] = v.z; As[a_kf*4+3][row] = v.w;
        }
        #pragma unroll
        for (int p = 0; p < 2; ++p) {
            int kr = b_kr + p * 8;
            *(float4*)&Bs[kr][b_nf*4] =
                *(const float4*)&B[(size_t)(k0 + kr) * ldb + n0 + b_nf * 4];
        }
        __syncthreads();
        #pragma unroll
        for (int kk = 0; kk < 16; ++kk) {
            float4 a0 = *(const float4*)&As[kk][tm*8];
            float4 a1 = *(const float4*)&As[kk][tm*8+4];
            ulonglong2 b0 = *(const ulonglong2*)&Bs[kk][tn*8];
            ulonglong2 b1 = *(const ulonglong2*)&Bs[kk][tn*8+4];
            unsigned long long ap;
            ap = pk2(a0.x); fma2(acc[0][0],ap,b0.x); fma2(acc[0][1],ap,b0.y); fma2(acc[0][2],ap,b1.x); fma2(acc[0][3],ap,b1.y);
            ap = pk2(a0.y); fma2(acc[1][0],ap,b0.x); fma2(acc[1][1],ap,b0.y); fma2(acc[1][2],ap,b1.x); fma2(acc[1][3],ap,b1.y);
            ap = pk2(a0.z); fma2(acc[2][0],ap,b0.x); fma2(acc[2][1],ap,b0.y); fma2(acc[2][2],ap,b1.x); fma2(acc[2][3],ap,b1.y);
            ap = pk2(a0.w); fma2(acc[3][0],ap,b0.x); fma2(acc[3][1],ap,b0.y); fma2(acc[3][2],ap,b1.x); fma2(acc[3][3],ap,b1.y);
            ap = pk2(a1.x); fma2(acc[4][0],ap,b0.x); fma2(acc[4][1],ap,b0.y); fma2(acc[4][2],ap,b1.x); fma2(acc[4][3],ap,b1.y);
            ap = pk2(a1.y); fma2(acc[5][0],ap,b0.x); fma2(acc[5][1],ap,b0.y); fma2(acc[5][2],ap,b1.x); fma2(acc[5][3],ap,b1.y);
            ap = pk2(a1.z); fma2(acc[6][0],ap,b0.x); fma2(acc[6][1],ap,b0.y); fma2(acc[6][2],ap,b1.x); fma2(acc[6][3],ap,b1.y);
            ap = pk2(a1.w); fma2(acc[7][0],ap,b0.x); fma2(acc[7][1],ap,b0.y); fma2(acc[7][2],ap,b1.x); fma2(acc[7][3],ap,b1.y);
        }
        __syncthreads();
    }
    #pragma unroll
    for (int i = 0; i < 8; ++i) {
        int row = m0 + tm * 8 + i;
        #pragma unroll
        for (int p = 0; p < 4; ++p) {
            float2 v = up2(acc[i][p]);
            int col = n0 + tn * 8 + p * 2;
            float r0 = v.x + bias[col], r1 = v.y + bias[col + 1];
            if (EPI == 1) { r0 = fmaxf(r0, 0.f); r1 = fmaxf(r1, 0.f); }
            *(float2*)&C[(size_t)row * N + col] = make_float2(r0, r1);
        }
    }
}

// --------------- fc2: HMMA split-bf16 GEMM D = F1 @ Wt^T --------------------
// grid (26 m, 79 n), 256 thr, tile 128x128, K=512 in 16 k32 stages
#define ROWB   80                      // padded bf16 row: 32 elems (64B) + 16B pad
#define ARR_B  (128*ROWB)              // 10240 B per operand array
#define STG_B  (4*ARR_B)               // 40960 B per stage
#define FC2_DSMEM (2*STG_B)            // 81920 B

__device__ __forceinline__ void fc2_load_stage(uint32_t sb, int tid,
                                               int m0, int n0, int k0)
{
    int c0 = tid * 2;
    #pragma unroll
    for (int a = 0; a < 4; ++a) {
        const __nv_bfloat16* src = (a == 0) ? g_F1h : (a == 1) ? g_F1l
                                 : (a == 2) ? g_Wth : g_Wtl;
        int rb = (a < 2) ? m0 : n0;
        #pragma unroll
        for (int u = 0; u < 2; ++u) {
            int c = c0 + u, r = c >> 2, q = c & 3;
            cpa16(sb + a * ARR_B + r * ROWB + q * 16,
                  src + (size_t)(rb + r) * UNITS + k0 + q * 8);
        }
    }
}

__global__ __launch_bounds__(256)
void fc2_mma(const float* __restrict__ bias, float* __restrict__ out)
{
    extern __shared__ __align__(16) unsigned char smem[];
    const uint32_t sbase = smem_u32(smem);
    const int tid = threadIdx.x, lane = tid & 31, wid = tid >> 5;
    const int wm = wid & 3, wn = wid >> 2;
    const int m0 = blockIdx.x * 128, n0 = blockIdx.y * 128;

    float acc[2][8][4];
    #pragma unroll
    for (int i = 0; i < 2; ++i)
        #pragma unroll
        for (int j = 0; j < 8; ++j)
            #pragma unroll
            for (int q = 0; q < 4; ++q) acc[i][j][q] = 0.f;

    const int a_row = wm * 32 + ((lane >> 3) & 1) * 8 + (lane & 7);
    const uint32_t a_koff = (lane >> 4) * 16;
    const int b_row = wn * 64 + (lane >> 4) * 8 + (lane & 7);
    const uint32_t b_koff = ((lane >> 3) & 1) * 16;

    fc2_load_stage(sbase, tid, m0, n0, 0);
    CP_COMMIT();

    for (int ks = 0; ks < 16; ++ks) {
        if (ks + 1 < 16) {
            fc2_load_stage(sbase + ((ks + 1) & 1) * STG_B, tid, m0, n0,
                           (ks + 1) * 32);
            CP_COMMIT();
            cp_wait<1>();
        } else {
            cp_wait<0>();
        }
        __syncthreads();

        const uint32_t sAh = sbase + (ks & 1) * STG_B;
        const uint32_t sAl = sAh + ARR_B;
        const uint32_t sBh = sAh + 2 * ARR_B;
        const uint32_t sBl = sAh + 3 * ARR_B;

        #pragma unroll
        for (int kk = 0; kk < 2; ++kk) {
            uint32_t ah[2][4], al[2][4];
            #pragma unroll
            for (int i = 0; i < 2; ++i) {
                uint32_t ao = (uint32_t)(a_row + i * 16) * ROWB + a_koff + kk * 32;
                ldsm4(ah[i], sAh + ao);
                ldsm4(al[i], sAl + ao);
            }
            uint32_t bh[4][4], bl[4][4];
            #pragma unroll
            for (int jj = 0; jj < 4; ++jj) {
                uint32_t bo = (uint32_t)(b_row + jj * 16) * ROWB + b_koff + kk * 32;
                ldsm4(bh[jj], sBh + bo);
                ldsm4(bl[jj], sBl + bo);
            }
            #pragma unroll
            for (int i = 0; i < 2; ++i)
                #pragma unroll
                for (int j = 0; j < 8; ++j) {
                    const uint32_t* ph = bh[j >> 1] + (j & 1) * 2;
                    const uint32_t* pl = bl[j >> 1] + (j & 1) * 2;
                    mma16816(acc[i][j], ah[i], ph);
                    mma16816(acc[i][j], ah[i], pl);
                    mma16816(acc[i][j], al[i], ph);
                }
        }
        __syncthreads();
    }

    // epilogue: remap row t*64+b -> (b*52+t), add bias; SCALAR stores
    // (VOCAB=10001 is odd -> odd rows are only 4B-aligned; float2 would fault)
    #pragma unroll
    for (int i = 0; i < 2; ++i) {
        #pragma unroll
        for (int half = 0; half < 2; ++half) {
            int row = m0 + wm * 32 + i * 16 + (lane >> 2) + half * 8;
            int tt = row >> 6, bb = row & 63;
            float* o = out + (size_t)(bb * TSTEPS + tt) * VOCAB;
            #pragma unroll
            for (int j = 0; j < 8; ++j) {
                int col = n0 + wn * 64 + j * 8 + (lane & 3) * 2;
                float v0 = acc[i][j][half * 2];
                float v1 = acc[i][j][half * 2 + 1];
                if (col < VOCAB)     o[col]     = v0 + __ldg(&bias[col]);
                if (col + 1 < VOCAB) o[col + 1] = v1 + __ldg(&bias[col + 1]);
            }
        }
    }
}

// --------------------- prep: transpose + bf16-split fc2 W -------------------
__global__ __launch_bounds__(256)
void k_prep_w(const float* __restrict__ W)
{
    __shared__ float s[32][33];
    int n0 = blockIdx.x * 32, k0 = blockIdx.y * 32;
    int tx = threadIdx.x & 31, ty = threadIdx.x >> 5;
    #pragma unroll
    for (int p = 0; p < 4; ++p) {
        int k = ty + p * 8, n = n0 + tx;
        s[k][tx] = (n < VOCAB) ? W[(size_t)(k0 + k) * VOCAB + n] : 0.f;
    }
    __syncthreads();
    #pragma unroll
    for (int p = 0; p < 4; ++p) {
        int nl = ty + p * 8;
        size_t oi = (size_t)(n0 + nl) * UNITS + (k0 + tx);
        float v = s[tx][nl];
        __nv_bfloat16 hi = __float2bfloat16(v);
        g_Wth[oi] = hi;
        g_Wtl[oi] = __float2bfloat16(v - __bfloat162float(hi));
    }
}

__global__ __launch_bounds__(256)
void k_split_f1()
{
    int i = blockIdx.x * 256 + threadIdx.x;
    if (i < MTB * UNITS) {
        float v = g_F1[i];
        __nv_bfloat16 hi = __float2bfloat16(v);
        g_F1h[i] = hi;
        g_F1l[i] = __float2bfloat16(v - __bfloat162float(hi));
    }
}

// ------------------- small GEMM body: 64 x 64 tile, K-slice 64 --------------
__device__ __forceinline__ void sg64(const float* __restrict__ A,
                                     const float* __restrict__ Bp, int ldb,
                                     float* __restrict__ C, int ldc,
                                     int k0, int n0)
{
    __shared__ __align__(16) float As[64][64];
    __shared__ __align__(16) float Bs[64][64];
    const int tid = threadIdx.x;
    {
        int a_m = tid & 63, a_kq = tid >> 6;
        #pragma unroll
        for (int i = 0; i < 4; ++i) {
            int kk = a_kq * 16 + i * 4;
            float4 v = *(const float4*)&A[a_m * 512 + k0 + kk];
            As[kk+0][a_m] = v.x; As[kk+1][a_m] = v.y;
            As[kk+2][a_m] = v.z; As[kk+3][a_m] = v.w;
        }
        int b_n4 = tid & 15, b_kr = tid >> 4;
        #pragma unroll
        for (int p = 0; p < 4; ++p) {
            int kr = b_kr + p * 16;
            *(float4*)&Bs[kr][b_n4 * 4] =
                *(const float4*)&Bp[(size_t)(k0 + kr) * ldb + n0 + b_n4 * 4];
        }
    }
    __syncthreads();
    const int tm = tid >> 4, tn = tid & 15;
    unsigned long long acc[4][2] = {};
    #pragma unroll 16
    for (int kk = 0; kk < 64; ++kk) {
        float4 a = *(const float4*)&As[kk][tm*4];
        ulonglong2 b = *(const ulonglong2*)&Bs[kk][tn*4];
        unsigned long long ap;
        ap = pk2(a.x); fma2(acc[0][0],ap,b.x); fma2(acc[0][1],ap,b.y);
        ap = pk2(a.y); fma2(acc[1][0],ap,b.x); fma2(acc[1][1],ap,b.y);
        ap = pk2(a.z); fma2(acc[2][0],ap,b.x); fma2(acc[2][1],ap,b.y);
        ap = pk2(a.w); fma2(acc[3][0],ap,b.x); fma2(acc[3][1],ap,b.y);
    }
    #pragma unroll
    for (int r = 0; r < 4; ++r) {
        float2 v0 = up2(acc[r][0]), v1 = up2(acc[r][1]);
        float* c = &C[(size_t)(tm*4+r)*ldc + n0 + tn*4];
        c[0]=v0.x; c[1]=v0.y; c[2]=v1.x; c[3]=v1.y;
    }
}

__global__ __launch_bounds__(256)
void k_step1(const float* __restrict__ W2, const float* __restrict__ rk)
{
    int xb = blockIdx.x, sp = blockIdx.y;
    int k0 = sp * 64;
    if (xb < 8)
        sg64(g_h, W2, 512,  g_hW2p + sp * (B_SZ*UNITS),   512,  k0, xb * 64);
    else
        sg64(g_h, rk, 1536, g_ghp  + sp * (B_SZ*3*UNITS), 1536, k0, (xb - 8) * 64);
}

__global__ __launch_bounds__(256)
void k_step3a(const float* __restrict__ gk)
{
    int xb = blockIdx.x, sp = blockIdx.y;
    sg64(g_x, gk, 1536, g_gxp + sp * (B_SZ*3*UNITS), 1536, sp * 64, xb * 64);
}

__global__ __launch_bounds__(512)
void k_attn(const float* __restrict__ W2_b, const float* __restrict__ V_W,
            const float* __restrict__ V_b,  const float* __restrict__ emb,
            const int* __restrict__ label, int t)
{
    __shared__ float s_hw2[512], s_vw[512], s_sc[64], s_ctx[2][256];
    const int b = blockIdx.x, tid = threadIdx.x;
    {
        float s = W2_b[tid];
        #pragma unroll
        for (int sp = 0; sp < NSPLIT; ++sp) s += g_hW2p[sp*(B_SZ*UNITS) + b*512 + tid];
        s_hw2[tid] = s;
        s_vw[tid] = V_W[tid];
    }
    __syncthreads();
    {
        int w = tid >> 5, lane = tid & 31;
        float vb = V_b[0];
        #pragma unroll
        for (int j = 0; j < 4; ++j) {
            int l = w * 4 + j;
            const float* fw = g_featW1 + (size_t)(b * 64 + l) * 512;
            float p = 0.f;
            #pragma unroll
            for (int i = 0; i < 16; ++i) {
                int u = lane + i * 32;
                p += s_vw[u] * fast_tanh(fw[u] + s_hw2[u]);
            }
            #pragma unroll
            for (int off = 16; off >= 1; off >>= 1)
                p += __shfl_xor_sync(0xffffffffu, p, off);
            if (lane == 0) s_sc[l] = p + vb;
        }
    }
    __syncthreads();
    if (tid < 32) {
        float s0 = s_sc[tid], s1 = s_sc[tid + 32];
        float m = fmaxf(s0, s1);
        #pragma unroll
        for (int off = 16; off >= 1; off >>= 1)
            m = fmaxf(m, __shfl_xor_sync(0xffffffffu, m, off));
        float e0 = __expf(s0 - m), e1 = __expf(s1 - m);
        float sum = e0 + e1;
        #pragma unroll
        for (int off = 16; off >= 1; off >>= 1)
            sum += __shfl_xor_sync(0xffffffffu, sum, off);
        float inv = __fdividef(1.0f, sum);
        s_sc[tid] = e0 * inv; s_sc[tid + 32] = e1 * inv;
    }
    __syncthreads();
    {
        int u = tid & 255, half = tid >> 8;
        float c = 0.f;
        #pragma unroll 8
        for (int l = half * 32; l < half * 32 + 32; ++l)
            c += s_sc[l] * g_feat[(size_t)(b * 64 + l) * 256 + u];
        s_ctx[half][u] = c;
    }
    __syncthreads();
    if (tid < 256) {
        g_x[b * 512 + tid] = s_ctx[0][tid] + s_ctx[1][tid];
    } else {
        int u = tid - 256;
        int tok = (t == 0) ? 3 : label[b * TSTEPS + t - 1];
        g_x[b * 512 + 256 + u] = emb[(size_t)tok * 256 + u];
    }
}

__global__ __launch_bounds__(256)
void k_gates(const float* __restrict__ gb, int t)
{
    int idx = blockIdx.x * 256 + threadIdx.x;
    int b = idx >> 9, u = idx & 511;
    float gxz = 0, gxr = 0, gxh = 0, ghz = 0, ghr = 0, ghh = 0;
    #pragma unroll
    for (int s = 0; s < NSPLIT; ++s) {
        int base = s * (B_SZ*3*UNITS) + b * 1536 + u;
        gxz += g_gxp[base]; gxr += g_gxp[base + 512]; gxh += g_gxp[base + 1024];
        ghz += g_ghp[base]; ghr += g_ghp[base + 512]; ghh += g_ghp[base + 1024];
    }
    float xz = gxz + gb[u],        xr = gxr + gb[512 + u],  xh = gxh + gb[1024 + u];
    float hz = ghz + gb[1536 + u], hr = ghr + gb[2048 + u], hh = ghh + gb[2560 + u];
    float z = fast_sigm(xz + hz);
    float r = fast_sigm(xr + hr);
    float n = fast_tanh(xh + r * hh);
    float hold = g_h[idx];
    float hn = z * hold + (1.0f - z) * n;
    g_h[idx] = hn;
    g_H[((size_t)t * 64 + b) * 512 + u] = hn;
}

__global__ void k_zero_h() {
    int i = blockIdx.x * 256 + threadIdx.x;
    if (i < B_SZ * UNITS) g_h[i] = 0.f;
}
__global__ void k_labels(const int* __restrict__ label, float* __restrict__ out) {
    int i = blockIdx.x * 256 + threadIdx.x;
    if (i < B_SZ * TSTEPS) out[PROBA_ELEMS + i] = (float)label[i];
}

// ---------------------------------------------------------------------------
extern "C" void kernel_launch(void* const* d_in, const int* in_sizes, int n_in,
                              void* d_out, int out_size)
{
    const float* data    = (const float*)d_in[0];
    const int*   label   = (const int*)  d_in[1];
    const float* dense_W = (const float*)d_in[2];
    const float* dense_b = (const float*)d_in[3];
    const float* emb     = (const float*)d_in[4];
    const float* gru_k   = (const float*)d_in[5];
    const float* gru_rk  = (const float*)d_in[6];
    const float* gru_b   = (const float*)d_in[7];
    const float* fc1_W   = (const float*)d_in[8];
    const float* fc1_b   = (const float*)d_in[9];
    const float* fc2_W   = (const float*)d_in[10];
    const float* fc2_b   = (const float*)d_in[11];
    const float* W1      = (const float*)d_in[12];
    const float* W1_b    = (const float*)d_in[13];
    const float* W2      = (const float*)d_in[14];
    const float* W2_b    = (const float*)d_in[15];
    const float* V_W     = (const float*)d_in[16];
    const float* V_b     = (const float*)d_in[17];
    float* out = (float*)d_out;

    float *feat, *featW1, *H, *F1;
    cudaGetSymbolAddress((void**)&feat,   g_feat);
    cudaGetSymbolAddress((void**)&featW1, g_featW1);
    cudaGetSymbolAddress((void**)&H,      g_H);
    cudaGetSymbolAddress((void**)&F1,     g_F1);

    cudaFuncSetAttribute(fc2_mma, cudaFuncAttributeMaxDynamicSharedMemorySize,
                         FC2_DSMEM);

    k_zero_h<<<128, 256>>>();
    k_prep_w<<<dim3(NPAD/32, UNITS/32), 256>>>(fc2_W);

    sgemm<1><<<dim3(EMB/64, ML/128), 128>>>(data, dense_W, dense_b, feat,
                                            ML, EMB, FEATD, EMB);
    sgemm<0><<<dim3(UNITS/64, ML/128), 128>>>(feat, W1, W1_b, featW1,
                                              ML, UNITS, EMB, UNITS);

    for (int t = 0; t < TSTEPS; ++t) {
        k_step1<<<dim3(32, NSPLIT), 256>>>(W2, gru_rk);
        k_attn <<<B_SZ, 512>>>(W2_b, V_W, V_b, emb, label, t);
        k_step3a<<<dim3(24, NSPLIT), 256>>>(gru_k);
        k_gates<<<128, 256>>>(gru_b, t);
    }

    sgemm<0><<<dim3(UNITS/64, MTB/128), 128>>>(H, fc1_W, fc1_b, F1,
                                               MTB, UNITS, UNITS, UNITS);
    k_split_f1<<<(MTB*UNITS + 255)/256, 256>>>();

    fc2_mma<<<dim3(MTB/128, NPAD/128), 256, FC2_DSMEM>>>(fc2_b, out);

    if ((size_t)out_size >= PROBA_ELEMS + (size_t)B_SZ * TSTEPS)
        k_labels<<<(B_SZ * TSTEPS + 255) / 256, 256>>>(label, out);
}